// round 12
// baseline (speedup 1.0000x reference)
#include <cuda_runtime.h>

#define CC   2
#define HH   200
#define WW   200
#define NN   200
#define HWN  (HH*WW*NN)
#define N4   (NN/4)                     // 50 float4 groups per (h,w)
#define NGROUPS (HH*WW*N4)              // 2,000,000
#define GRID_CTAS 1184                  // 148 SMs x 8 CTAs: exactly one wave
#define CHUNK 512                       // groups per steal (2 per thread)

// Factorized per-axis cell tables (int8):
//   g_cx[w*NN + n] = cx in {0,1}, or -1 if x outside [x1,x2]
//   g_cy[h*NN + n] = cy in {0,1}, or -1 if y outside [y1,y2]
__device__ signed char g_cx[WW * NN];
__device__ signed char g_cy[HH * NN];
__device__ unsigned int g_counter;      // dynamic chunk counter

__global__ void prep_kernel(const float* __restrict__ rois) {
    int idx = blockIdx.x * blockDim.x + threadIdx.x;   // [0, 2*200*200)
    if (idx == 0) g_counter = 0;        // reset scheduler each launch/replay
    if (idx >= 2 * WW * NN) return;

    int axis = idx / (WW * NN);     // 0 = x, 1 = y
    int rem  = idx % (WW * NN);
    int p    = rem / NN;            // pixel coord (w or h)
    int n    = rem % NN;

    float lo = rois[4 * n + (axis ? 1 : 0)];   // x1 or y1
    float hi = rois[4 * n + (axis ? 3 : 2)];   // x2 or y2
    float cl = fmaxf(hi - lo, 1.0f);
    // double-precision reciprocal so (p-lo)*s tracks fp32 CC*(p-lo)/cl to ~1 ulp
    float s  = (float)((double)CC / (double)cl);

    float pf = (float)p;
    signed char v = -1;
    if (pf >= lo && pf <= hi) {
        int c = (int)floorf((pf - lo) * s);
        c = min(max(c, 0), CC - 1);
        v = (signed char)c;
    }
    if (axis == 0) g_cx[p * NN + n] = v;
    else           g_cy[p * NN + n] = v;
}

// Gather one group's 4 values into v; returns output base index.
__device__ __forceinline__ void gather_group(int gi,
                                             const float* __restrict__ data,
                                             int& base_out, float* v) {
    int n4 = gi % N4;
    int hw = gi / N4;
    int w  = hw % WW;
    int h  = hw / WW;
    int base = hw * NN + n4 * 4;
    base_out = base;

    char4 cx4 = *reinterpret_cast<const char4*>(g_cx + w * NN + n4 * 4);
    char4 cy4 = *reinterpret_cast<const char4*>(g_cy + h * NN + n4 * 4);
    signed char cxs[4] = {cx4.x, cx4.y, cx4.z, cx4.w};
    signed char cys[4] = {cy4.x, cy4.y, cy4.z, cy4.w};

    #pragma unroll
    for (int i = 0; i < 4; i++) {
        int cx = cxs[i];
        int cy = cys[i];
        float val = 0.0f;
        if ((cx | cy) >= 0) {
            int cell = cy * CC + cx;
            val = __ldg(data + (size_t)cell * HWN + base + i);
        }
        v[i] = val;
    }
}

// Persistent single-wave kernel with DYNAMIC chunk stealing: whole-kernel
// time is no longer bound by the slowest statically-assigned CTA.
__global__ void __launch_bounds__(256)
crop_split_kernel(const float* __restrict__ data, float* __restrict__ out) {
    __shared__ unsigned int s_base[2];
    int tid = threadIdx.x;

    for (unsigned int it = 0; ; it++) {
        if (tid == 0)
            s_base[it & 1] = atomicAdd(&g_counter, (unsigned int)CHUNK);
        __syncthreads();
        unsigned int cbase = s_base[it & 1];
        if (cbase >= (unsigned int)NGROUPS) break;

        int gi0 = (int)cbase + tid;          // group 1
        int gi1 = gi0 + 256;                 // group 2 (same chunk)

        // pair-batched: all 8 predicated gathers in flight before stores
        int b0, b1;
        float v0[4], v1[4];
        bool ok0 = (gi0 < NGROUPS);
        bool ok1 = (gi1 < NGROUPS);
        if (ok0) gather_group(gi0, data, b0, v0);
        if (ok1) gather_group(gi1, data, b1, v1);
        if (ok0) *reinterpret_cast<float4*>(out + b0) =
                     make_float4(v0[0], v0[1], v0[2], v0[3]);
        if (ok1) *reinterpret_cast<float4*>(out + b1) =
                     make_float4(v1[0], v1[1], v1[2], v1[3]);
    }
}

extern "C" void kernel_launch(void* const* d_in, const int* in_sizes, int n_in,
                              void* d_out, int out_size) {
    const float* data = (const float*)d_in[0];   // (4, H, W, N) fp32
    const float* rois = (const float*)d_in[1];   // (N, 4) fp32
    float* out = (float*)d_out;                  // (H, W, N) fp32

    int prep_elems = 2 * WW * NN;                // 80000
    prep_kernel<<<(prep_elems + 255) / 256, 256>>>(rois);

    crop_split_kernel<<<GRID_CTAS, 256>>>(data, out);
}

// round 13
// speedup vs baseline: 1.1338x; 1.1338x over previous
#include <cuda_runtime.h>

#define CC   2
#define HH   200
#define WW   200
#define NN   200
#define HWN  (HH*WW*NN)
#define N4   (NN/4)                     // 50 float4 groups per (h,w)
#define NGROUPS (HH*WW*N4)              // 2,000,000
#define GRID_CTAS 1184                  // 148 SMs x 8 resident slots: one wave
#define NTHREADS (GRID_CTAS*256)        // 303,104

// Factorized per-axis cell tables (int8):
//   g_cx[w*NN + n] = cx in {0,1}, or -1 if x outside [x1,x2]
//   g_cy[h*NN + n] = cy in {0,1}, or -1 if y outside [y1,y2]
__device__ signed char g_cx[WW * NN];
__device__ signed char g_cy[HH * NN];

__global__ void prep_kernel(const float* __restrict__ rois) {
    int idx = blockIdx.x * blockDim.x + threadIdx.x;   // [0, 2*200*200)
    if (idx >= 2 * WW * NN) return;

    int axis = idx / (WW * NN);     // 0 = x, 1 = y
    int rem  = idx % (WW * NN);
    int p    = rem / NN;            // pixel coord (w or h)
    int n    = rem % NN;

    float lo = rois[4 * n + (axis ? 1 : 0)];   // x1 or y1
    float hi = rois[4 * n + (axis ? 3 : 2)];   // x2 or y2
    float cl = fmaxf(hi - lo, 1.0f);
    // double-precision reciprocal so (p-lo)*s tracks fp32 CC*(p-lo)/cl to ~1 ulp
    float s  = (float)((double)CC / (double)cl);

    float pf = (float)p;
    signed char v = -1;
    if (pf >= lo && pf <= hi) {
        int c = (int)floorf((pf - lo) * s);
        c = min(max(c, 0), CC - 1);
        v = (signed char)c;
    }
    if (axis == 0) g_cx[p * NN + n] = v;
    else           g_cy[p * NN + n] = v;
}

// Gather one group's 4 values into v; returns output base index.
__device__ __forceinline__ void gather_group(int gi,
                                             const float* __restrict__ data,
                                             int& base_out, float* v) {
    int n4 = gi % N4;
    int hw = gi / N4;
    int w  = hw % WW;
    int h  = hw / WW;
    int base = hw * NN + n4 * 4;
    base_out = base;

    char4 cx4 = *reinterpret_cast<const char4*>(g_cx + w * NN + n4 * 4);
    char4 cy4 = *reinterpret_cast<const char4*>(g_cy + h * NN + n4 * 4);
    signed char cxs[4] = {cx4.x, cx4.y, cx4.z, cx4.w};
    signed char cys[4] = {cy4.x, cy4.y, cy4.z, cy4.w};

    #pragma unroll
    for (int i = 0; i < 4; i++) {
        int cx = cxs[i];
        int cy = cys[i];
        float val = 0.0f;
        if ((cx | cy) >= 0) {
            int cell = cy * CC + cx;
            val = __ldg(data + (size_t)cell * HWN + base + i);
        }
        v[i] = val;
    }
}

// Persistent single-wave kernel; QUAD-batched grid-stride: 16 predicated
// gathers + 4 table pairs in flight before any store. 48 warps/SM x MLP 16.
__global__ void __launch_bounds__(256, 6)
crop_split_kernel(const float* __restrict__ data, float* __restrict__ out) {
    int t = blockIdx.x * 256 + threadIdx.x;

    // NGROUPS / NTHREADS = 6.598 -> 4-batch + 2-batch + tail
    int b0, b1, b2, b3;
    float v0[4], v1[4], v2[4], v3[4];

    int gi = t;
    gather_group(gi,               data, b0, v0);
    gather_group(gi + 1*NTHREADS,  data, b1, v1);
    gather_group(gi + 2*NTHREADS,  data, b2, v2);
    gather_group(gi + 3*NTHREADS,  data, b3, v3);
    *reinterpret_cast<float4*>(out + b0) = make_float4(v0[0], v0[1], v0[2], v0[3]);
    *reinterpret_cast<float4*>(out + b1) = make_float4(v1[0], v1[1], v1[2], v1[3]);
    *reinterpret_cast<float4*>(out + b2) = make_float4(v2[0], v2[1], v2[2], v2[3]);
    *reinterpret_cast<float4*>(out + b3) = make_float4(v3[0], v3[1], v3[2], v3[3]);

    gi += 4 * NTHREADS;
    gather_group(gi,              data, b0, v0);
    gather_group(gi + NTHREADS,   data, b1, v1);
    *reinterpret_cast<float4*>(out + b0) = make_float4(v0[0], v0[1], v0[2], v0[3]);
    *reinterpret_cast<float4*>(out + b1) = make_float4(v1[0], v1[1], v1[2], v1[3]);

    gi += 2 * NTHREADS;
    if (gi < NGROUPS) {
        gather_group(gi, data, b0, v0);
        *reinterpret_cast<float4*>(out + b0) = make_float4(v0[0], v0[1], v0[2], v0[3]);
    }
}

extern "C" void kernel_launch(void* const* d_in, const int* in_sizes, int n_in,
                              void* d_out, int out_size) {
    const float* data = (const float*)d_in[0];   // (4, H, W, N) fp32
    const float* rois = (const float*)d_in[1];   // (N, 4) fp32
    float* out = (float*)d_out;                  // (H, W, N) fp32

    int prep_elems = 2 * WW * NN;                // 80000
    prep_kernel<<<(prep_elems + 255) / 256, 256>>>(rois);

    crop_split_kernel<<<GRID_CTAS, 256>>>(data, out);
}

// round 14
// speedup vs baseline: 1.1509x; 1.0151x over previous
#include <cuda_runtime.h>

#define CC   2
#define HH   200
#define WW   200
#define NN   200
#define HWN  (HH*WW*NN)
#define N4   (NN/4)                     // 50 float4 groups per (h,w)
#define NGROUPS (HH*WW*N4)              // 2,000,000
#define GRID_CTAS 1184                  // 148 SMs x 8 CTAs: exactly one wave
#define NTHREADS (GRID_CTAS*256)        // 303,104

// Factorized per-axis cell tables (int8):
//   g_cx[w*NN + n] = cx in {0,1}, or -1 if x outside [x1,x2]
//   g_cy[h*NN + n] = cy in {0,1}, or -1 if y outside [y1,y2]
__device__ signed char g_cx[WW * NN];
__device__ signed char g_cy[HH * NN];

__global__ void prep_kernel(const float* __restrict__ rois) {
    int idx = blockIdx.x * blockDim.x + threadIdx.x;   // [0, 2*200*200)
    if (idx >= 2 * WW * NN) return;

    int axis = idx / (WW * NN);     // 0 = x, 1 = y
    int rem  = idx % (WW * NN);
    int p    = rem / NN;            // pixel coord (w or h)
    int n    = rem % NN;

    float lo = rois[4 * n + (axis ? 1 : 0)];   // x1 or y1
    float hi = rois[4 * n + (axis ? 3 : 2)];   // x2 or y2
    float cl = fmaxf(hi - lo, 1.0f);
    // double-precision reciprocal so (p-lo)*s tracks fp32 CC*(p-lo)/cl to ~1 ulp
    float s  = (float)((double)CC / (double)cl);

    float pf = (float)p;
    signed char v = -1;
    if (pf >= lo && pf <= hi) {
        int c = (int)floorf((pf - lo) * s);
        c = min(max(c, 0), CC - 1);
        v = (signed char)c;
    }
    if (axis == 0) g_cx[p * NN + n] = v;
    else           g_cy[p * NN + n] = v;
}

__device__ __forceinline__ void do_group(int gi,
                                         const float* __restrict__ data,
                                         float* __restrict__ out) {
    int n4 = gi % N4;           // group of 4 consecutive n
    int hw = gi / N4;           // h*WW + w
    int w  = hw % WW;
    int h  = hw / WW;

    int base = hw * NN + n4 * 4;   // 16B aligned

    char4 cx4 = *reinterpret_cast<const char4*>(g_cx + w * NN + n4 * 4);
    char4 cy4 = *reinterpret_cast<const char4*>(g_cy + h * NN + n4 * 4);

    signed char cxs[4] = {cx4.x, cx4.y, cx4.z, cx4.w};
    signed char cys[4] = {cy4.x, cy4.y, cy4.z, cy4.w};

    float v[4];
    #pragma unroll
    for (int i = 0; i < 4; i++) {
        int cx = cxs[i];
        int cy = cys[i];
        float val = 0.0f;
        if ((cx | cy) >= 0) {
            int cell = cy * CC + cx;
            val = __ldg(data + (size_t)cell * HWN + base + i);
        }
        v[i] = val;
    }

    *reinterpret_cast<float4*>(out + base) = make_float4(v[0], v[1], v[2], v[3]);
}

// Persistent single-wave kernel: 1184 CTAs grid-stride over the 2M groups.
// No wave transitions; unroll 2 keeps two groups' loads in flight per thread.
__global__ void __launch_bounds__(256)
crop_split_kernel(const float* __restrict__ data, float* __restrict__ out) {
    int t = blockIdx.x * 256 + threadIdx.x;

    // NGROUPS / NTHREADS = 6.598 -> 6 full strided passes + partial 7th
    int gi = t;
    #pragma unroll 2
    for (int it = 0; it < 6; it++) {
        do_group(gi, data, out);
        gi += NTHREADS;
    }
    if (gi < NGROUPS)
        do_group(gi, data, out);
}

extern "C" void kernel_launch(void* const* d_in, const int* in_sizes, int n_in,
                              void* d_out, int out_size) {
    const float* data = (const float*)d_in[0];   // (4, H, W, N) fp32
    const float* rois = (const float*)d_in[1];   // (N, 4) fp32
    float* out = (float*)d_out;                  // (H, W, N) fp32

    int prep_elems = 2 * WW * NN;                // 80000
    prep_kernel<<<(prep_elems + 255) / 256, 256>>>(rois);

    crop_split_kernel<<<GRID_CTAS, 256>>>(data, out);
}

// round 15
// speedup vs baseline: 1.1533x; 1.0022x over previous
#include <cuda_runtime.h>

#define CC   2
#define HH   200
#define WW   200
#define NN   200
#define HWN  (HH*WW*NN)
#define N4   (NN/4)                     // 50 float4 groups per (h,w)
#define NGROUPS (HH*WW*N4)              // 2,000,000
#define GRID_CTAS 1184                  // 148 SMs x 8 CTAs: exactly one wave
#define NTHREADS (GRID_CTAS*256)        // 303,104

// Factorized per-axis cell tables (int8):
//   g_cx[w*NN + n] = cx in {0,1}, or -1 if x outside [x1,x2]
//   g_cy[h*NN + n] = cy in {0,1}, or -1 if y outside [y1,y2]
__device__ signed char g_cx[WW * NN];
__device__ signed char g_cy[HH * NN];

__global__ void prep_kernel(const float* __restrict__ rois) {
    int idx = blockIdx.x * blockDim.x + threadIdx.x;   // [0, 2*200*200)
    if (idx < 2 * WW * NN) {
        int axis = idx / (WW * NN);     // 0 = x, 1 = y
        int rem  = idx % (WW * NN);
        int p    = rem / NN;            // pixel coord (w or h)
        int n    = rem % NN;

        float lo = rois[4 * n + (axis ? 1 : 0)];   // x1 or y1
        float hi = rois[4 * n + (axis ? 3 : 2)];   // x2 or y2
        float cl = fmaxf(hi - lo, 1.0f);
        // double-precision reciprocal so (p-lo)*s tracks fp32 CC*(p-lo)/cl to ~1 ulp
        float s  = (float)((double)CC / (double)cl);

        float pf = (float)p;
        signed char v = -1;
        if (pf >= lo && pf <= hi) {
            int c = (int)floorf((pf - lo) * s);
            c = min(max(c, 0), CC - 1);
            v = (signed char)c;
        }
        if (axis == 0) g_cx[p * NN + n] = v;
        else           g_cy[p * NN + n] = v;
    }
    // PDL: allow the dependent crop kernel to begin; its table reads are
    // gated by cudaGridDependencySynchronize() on the consumer side.
    cudaTriggerProgrammaticLaunchCompletion();
}

__device__ __forceinline__ void do_group(int gi,
                                         const float* __restrict__ data,
                                         float* __restrict__ out) {
    int n4 = gi % N4;           // group of 4 consecutive n
    int hw = gi / N4;           // h*WW + w
    int w  = hw % WW;
    int h  = hw / WW;

    int base = hw * NN + n4 * 4;   // 16B aligned

    char4 cx4 = *reinterpret_cast<const char4*>(g_cx + w * NN + n4 * 4);
    char4 cy4 = *reinterpret_cast<const char4*>(g_cy + h * NN + n4 * 4);

    signed char cxs[4] = {cx4.x, cx4.y, cx4.z, cx4.w};
    signed char cys[4] = {cy4.x, cy4.y, cy4.z, cy4.w};

    float v[4];
    #pragma unroll
    for (int i = 0; i < 4; i++) {
        int cx = cxs[i];
        int cy = cys[i];
        float val = 0.0f;
        if ((cx | cy) >= 0) {
            int cell = cy * CC + cx;
            val = __ldg(data + (size_t)cell * HWN + base + i);
        }
        v[i] = val;
    }

    *reinterpret_cast<float4*>(out + base) = make_float4(v[0], v[1], v[2], v[3]);
}

// Persistent single-wave kernel (R10 body). Launched with programmatic
// stream serialization: CTAs spin up and run the preamble during prep's
// tail; table reads wait on cudaGridDependencySynchronize().
__global__ void __launch_bounds__(256)
crop_split_kernel(const float* __restrict__ data, float* __restrict__ out) {
    int t = blockIdx.x * 256 + threadIdx.x;

    // Wait for prep's table writes (PDL consumer side).
    cudaGridDependencySynchronize();

    // NGROUPS / NTHREADS = 6.598 -> 6 full strided passes + partial 7th
    int gi = t;
    #pragma unroll 2
    for (int it = 0; it < 6; it++) {
        do_group(gi, data, out);
        gi += NTHREADS;
    }
    if (gi < NGROUPS)
        do_group(gi, data, out);
}

extern "C" void kernel_launch(void* const* d_in, const int* in_sizes, int n_in,
                              void* d_out, int out_size) {
    const float* data = (const float*)d_in[0];   // (4, H, W, N) fp32
    const float* rois = (const float*)d_in[1];   // (N, 4) fp32
    float* out = (float*)d_out;                  // (H, W, N) fp32

    int prep_elems = 2 * WW * NN;                // 80000
    prep_kernel<<<(prep_elems + 255) / 256, 256>>>(rois);

    // Launch crop with programmatic stream serialization (PDL).
    cudaLaunchConfig_t cfg = {};
    cfg.gridDim  = dim3(GRID_CTAS, 1, 1);
    cfg.blockDim = dim3(256, 1, 1);
    cudaLaunchAttribute attr[1];
    attr[0].id = cudaLaunchAttributeProgrammaticStreamSerialization;
    attr[0].val.programmaticStreamSerializationAllowed = 1;
    cfg.attrs = attr;
    cfg.numAttrs = 1;
    cudaLaunchKernelEx(&cfg, crop_split_kernel, data, out);
}